// round 9
// baseline (speedup 1.0000x reference)
#include <cuda_runtime.h>
#include <cuda_bf16.h>
#include <cstdint>

#define NT   8192   // tokens
#define DD   1024   // model dim
#define HH   4096   // hidden dim
#define NE   8      // experts
#define NENT_PAD 16512

// ------------------------- device scratch (no allocs) -------------------------
__device__ float g_w1t[(size_t)NE * HH * DD];   // rna(w1)^T : [E][H][D] (k-major)
__device__ float g_w2t[(size_t)NE * DD * HH];   // rna(w2)^T : [E][D][H] (k-major)
__device__ float g_xe [(size_t)NENT_PAD * DD];  // gathered rna inputs per entry
__device__ float g_h  [(size_t)NENT_PAD * HH];  // gelu(x@w1+b1), rna'd
__device__ float g_y  [(size_t)NENT_PAD * DD];  // h@w2+b2
__device__ float g_wts[NT * 2];
__device__ int   g_list[NE * NT];
__device__ int   g_t2e [NT * 2];
__device__ int   g_cnt [NE];

// ------------------------- helpers -------------------------
__device__ __forceinline__ uint32_t s2u(const void* p) {
    return (uint32_t)__cvta_generic_to_shared(p);
}
__device__ __forceinline__ float to_tf32(float v) {
    uint32_t u; asm("cvt.rna.tf32.f32 %0, %1;" : "=r"(u) : "f"(v));
    return __uint_as_float(u);
}
// gelu(x) = x * sigmoid(2*0.79788456*(x + 0.044715 x^3)); matches tanh-gelu to ~1e-7
__device__ __forceinline__ float gelu_fast(float x) {
    float z = x * fmaf(0.10294324f, x * x, 2.30220822f);  // 2u*log2(e)
    float ex; asm("ex2.approx.f32 %0, %1;" : "=f"(ex) : "f"(-z));
    float r;  asm("rcp.approx.f32 %0, %1;" : "=f"(r)  : "f"(1.0f + ex));
    return x * r;
}
__device__ __forceinline__ void cp16(uint32_t s, const void* g) {
    asm volatile("cp.async.cg.shared.global [%0], [%1], 16;" :: "r"(s), "l"(g));
}
__device__ __forceinline__ void ldm4(uint32_t a[4], uint32_t addr) {
    asm volatile("ldmatrix.sync.aligned.m8n8.x4.shared.b16 {%0,%1,%2,%3}, [%4];"
                 : "=r"(a[0]), "=r"(a[1]), "=r"(a[2]), "=r"(a[3]) : "r"(addr));
}
__device__ __forceinline__ void mma8u(float d[4], const uint32_t a[4],
                                      uint32_t b0, uint32_t b1) {
    asm volatile(
        "mma.sync.aligned.m16n8k8.row.col.f32.tf32.tf32.f32 "
        "{%0,%1,%2,%3}, {%4,%5,%6,%7}, {%8,%9}, {%0,%1,%2,%3};"
        : "+f"(d[0]), "+f"(d[1]), "+f"(d[2]), "+f"(d[3])
        : "r"(a[0]), "r"(a[1]), "r"(a[2]), "r"(a[3]), "r"(b0), "r"(b1));
}
__device__ __forceinline__ int expert_base(int e) {
    int b = 0;
    #pragma unroll
    for (int i = 0; i < NE; i++) b += (i < e) ? g_cnt[i] : 0;
    return b;
}

// ------------------------- small kernels -------------------------
__global__ void moe_reset_kernel() {
    if (threadIdx.x < NE) g_cnt[threadIdx.x] = 0;
}

// transpose per expert: src [E][R][C] -> dst [E][C][R], rna-rounded on output
__global__ void moe_transpose_kernel(const float* __restrict__ src,
                                     float* __restrict__ dst, int R, int C) {
    __shared__ float t[32][33];
    int e  = blockIdx.z;
    int c0 = blockIdx.x * 32, r0 = blockIdx.y * 32;
    const float* s = src + (size_t)e * R * C;
    float*       d = dst + (size_t)e * R * C;
    int tx = threadIdx.x;
    #pragma unroll
    for (int i = threadIdx.y; i < 32; i += 8)
        t[i][tx] = s[(size_t)(r0 + i) * C + c0 + tx];
    __syncthreads();
    #pragma unroll
    for (int i = threadIdx.y; i < 32; i += 8)
        d[(size_t)(c0 + i) * R + r0 + tx] = to_tf32(t[tx][i]);
}

__global__ void moe_gate_kernel(const float* __restrict__ x,
                                const float* __restrict__ gw,
                                const float* __restrict__ gb) {
    int warp = threadIdx.x >> 5, lane = threadIdx.x & 31;
    int t = blockIdx.x * 8 + warp;
    float acc[NE];
    #pragma unroll
    for (int e = 0; e < NE; e++) acc[e] = 0.f;
    const float* xr = x + (size_t)t * DD;
    for (int k = lane; k < DD; k += 32) {
        float xv = xr[k];
        const float4* g4 = (const float4*)(gw + (size_t)k * NE);
        float4 a = g4[0], b = g4[1];
        acc[0] = fmaf(xv, a.x, acc[0]); acc[1] = fmaf(xv, a.y, acc[1]);
        acc[2] = fmaf(xv, a.z, acc[2]); acc[3] = fmaf(xv, a.w, acc[3]);
        acc[4] = fmaf(xv, b.x, acc[4]); acc[5] = fmaf(xv, b.y, acc[5]);
        acc[6] = fmaf(xv, b.z, acc[6]); acc[7] = fmaf(xv, b.w, acc[7]);
    }
    #pragma unroll
    for (int off = 16; off > 0; off >>= 1)
        #pragma unroll
        for (int e = 0; e < NE; e++)
            acc[e] += __shfl_xor_sync(0xFFFFFFFFu, acc[e], off);
    if (lane == 0) {
        float l[NE];
        #pragma unroll
        for (int e = 0; e < NE; e++) l[e] = acc[e] + gb[e];
        int i0 = 0;
        #pragma unroll
        for (int e = 1; e < NE; e++) if (l[e] > l[i0]) i0 = e;
        int i1 = (i0 == 0) ? 1 : 0;
        #pragma unroll
        for (int e = 0; e < NE; e++) if (e != i0 && l[e] > l[i1]) i1 = e;
        float ex = __expf(l[i1] - l[i0]);
        float s  = 1.0f + ex;
        int s0 = atomicAdd(&g_cnt[i0], 1);
        g_list[i0 * NT + s0] = t * 2;
        int s1 = atomicAdd(&g_cnt[i1], 1);
        g_list[i1 * NT + s1] = t * 2 + 1;
        g_wts[t * 2]     = 1.0f / s;
        g_wts[t * 2 + 1] = ex / s;
    }
}

__global__ void moe_gather_kernel(const float* __restrict__ x) {
    int e = blockIdx.y, slot = blockIdx.x;
    if (slot >= g_cnt[e]) return;
    int tokj  = g_list[e * NT + slot];
    int entry = expert_base(e) + slot;
    if (threadIdx.x == 0) g_t2e[tokj] = entry;
    const float4* src = (const float4*)(x + (size_t)(tokj >> 1) * DD);
    float4*       dst = (float4*)(g_xe + (size_t)entry * DD);
    #pragma unroll
    for (int i = threadIdx.x; i < DD / 4; i += 128) {
        float4 v = src[i];
        v.x = to_tf32(v.x); v.y = to_tf32(v.y);
        v.z = to_tf32(v.z); v.w = to_tf32(v.w);
        dst[i] = v;
    }
}

__global__ void moe_combine_kernel(float* __restrict__ out) {
    int t = blockIdx.x;
    int e0 = g_t2e[2 * t], e1 = g_t2e[2 * t + 1];
    float w0 = g_wts[2 * t], w1 = g_wts[2 * t + 1];
    const float4* y0 = (const float4*)(g_y + (size_t)e0 * DD);
    const float4* y1 = (const float4*)(g_y + (size_t)e1 * DD);
    float4*       o  = (float4*)(out + (size_t)t * DD);
    #pragma unroll
    for (int i = threadIdx.x; i < DD / 4; i += 128) {
        float4 a = y0[i], b = y1[i];
        o[i] = make_float4(fmaf(w0, a.x, w1 * b.x), fmaf(w0, a.y, w1 * b.y),
                           fmaf(w0, a.z, w1 * b.z), fmaf(w0, a.w, w1 * b.w));
    }
}

// ------------------------- mma.sync tf32 GEMM -------------------------
// CTA tile 128x256; 512 threads / 16 warps (4/SMSP); warp grid 4m x 4n,
// warp tile 32x64. K chunk 32; both operands k-major stride 36, ldmatrix.x4.
// 4-stage cp.async pipeline, 1 barrier/chunk.
#define AST (128 * 36)
#define BST (256 * 36)
#define STG 4

template <int DO_GELU>
__global__ void __launch_bounds__(512, 1)
moe_ffn_gemm(const float* __restrict__ A, const float* __restrict__ B,
             const float* __restrict__ bias, float* __restrict__ Out,
             int K, int Ntot) {
    int e   = blockIdx.z;
    int cnt = g_cnt[e];
    int m0  = blockIdx.x * 128;
    if (m0 >= cnt) return;
    int base = expert_base(e);
    int n0   = blockIdx.y * 256;

    extern __shared__ float sm[];
    float* sA    = sm;
    float* sB    = sm + STG * AST;
    float* sBias = sB + STG * BST;

    int tid  = threadIdx.x;
    int lane = tid & 31, w = tid >> 5;
    int g = lane >> 2, tg = lane & 3;
    int wm = w & 3, wn = w >> 2;

    // A ldmatrix lanes: 0-7 rows r..r+7 k0 | 8-15 rows+8 k0 | 16-23 rows k4 | 24-31 rows+8 k4
    int arow = (lane & 7) + ((lane >> 3) & 1) * 8;
    int acol = (lane >> 4) * 4;
    uint32_t aLane = (uint32_t)(((wm * 32 + arow) * 36 + acol) * 4);
    // B ldmatrix lanes: 0-7 rows n..n+7 k0 | 8-15 rows k4 | 16-23 rows+8 k0 | 24-31 rows+8 k4
    int brow = (lane & 7) + ((lane >> 4) & 1) * 8;
    int bcol = ((lane >> 3) & 1) * 4;
    uint32_t bLane = (uint32_t)(((wn * 64 + brow) * 36 + bcol) * 4);

    if (tid < 256) sBias[tid] = bias[(size_t)e * Ntot + n0 + tid];

    const float* Ab = A + (size_t)(base + m0) * K;
    const float* Bb = B + ((size_t)e * Ntot + n0) * K;
    int C = K >> 5;

    // per chunk: A = 1024 cp16, B = 2048 cp16; 512 threads
    auto load_full = [&](int c, int s) {
        float* dA = sA + s * AST;
        #pragma unroll
        for (int j = 0; j < 2; j++) {
            int i = tid + j * 512;
            int m = i >> 3, kq = (i & 7) << 2;
            cp16(s2u(dA + m * 36 + kq), Ab + c * 32 + (size_t)m * K + kq);
        }
        float* dB = sB + s * BST;
        #pragma unroll
        for (int j = 0; j < 4; j++) {
            int i = tid + j * 512;
            int n = i >> 3, kq = (i & 7) << 2;
            cp16(s2u(dB + n * 36 + kq), Bb + c * 32 + (size_t)n * K + kq);
        }
        asm volatile("cp.async.commit_group;" ::: "memory");
    };
    auto load_slice = [&](int c, int s, int part) {  // parts 0..3
        if ((part & 1) == 0) {                       // A halves in parts 0,2
            int i = tid + (part >> 1) * 512;
            int m = i >> 3, kq = (i & 7) << 2;
            cp16(s2u(sA + s * AST + m * 36 + kq), Ab + c * 32 + (size_t)m * K + kq);
        }
        {
            int i = tid + part * 512;
            int n = i >> 3, kq = (i & 7) << 2;
            cp16(s2u(sB + s * BST + n * 36 + kq), Bb + c * 32 + (size_t)n * K + kq);
        }
    };

    auto ldfragA = [&](uint32_t af[2][4], int s, int ks) {
        uint32_t aBase = s2u(sA) + (uint32_t)s * (AST * 4) + aLane + (uint32_t)(ks * 32);
        #pragma unroll
        for (int mt = 0; mt < 2; mt++) ldm4(af[mt], aBase + (uint32_t)(mt * 2304));
    };
    auto ldfragB = [&](uint32_t bf[4][4], int s, int ks) {
        uint32_t bBase = s2u(sB) + (uint32_t)s * (BST * 4) + bLane + (uint32_t)(ks * 32);
        #pragma unroll
        for (int np = 0; np < 4; np++) ldm4(bf[np], bBase + (uint32_t)(np * 2304));
    };

    load_full(0, 0); load_full(1, 1); load_full(2, 2);

    float acc[2][8][4];
    #pragma unroll
    for (int mt = 0; mt < 2; mt++)
        #pragma unroll
        for (int nt = 0; nt < 8; nt++)
            #pragma unroll
            for (int q = 0; q < 4; q++) acc[mt][nt][q] = 0.f;

    int s = 0;
    for (int c = 0; c < C; c++) {
        if (c + 2 < C) { asm volatile("cp.async.wait_group 1;" ::: "memory"); }
        else           { asm volatile("cp.async.wait_group 0;" ::: "memory"); }
        __syncthreads();

        int sw = s + 3; if (sw >= STG) sw -= STG;
        bool ld = (c + 3 < C);
        #pragma unroll
        for (int ks = 0; ks < 4; ks++) {
            uint32_t af[2][4], bf[4][4];
            ldfragA(af, s, ks);
            ldfragB(bf, s, ks);
            if (ld) load_slice(c + 3, sw, ks);
            #pragma unroll
            for (int mt = 0; mt < 2; mt++)
                #pragma unroll
                for (int np = 0; np < 4; np++) {
                    mma8u(acc[mt][2 * np + 0], af[mt], bf[np][0], bf[np][1]);
                    mma8u(acc[mt][2 * np + 1], af[mt], bf[np][2], bf[np][3]);
                }
        }
        if (ld) asm volatile("cp.async.commit_group;" ::: "memory");
        s++; if (s >= STG) s = 0;
    }

    // epilogue: bias (+gelu+rna for FFN1), float2 stores
    #pragma unroll
    for (int mt = 0; mt < 2; mt++) {
        int r0 = m0 + wm * 32 + mt * 16 + g;
        #pragma unroll
        for (int half = 0; half < 2; half++) {
            int r = r0 + half * 8;
            if (r < cnt) {
                size_t orow = (size_t)(base + r) * Ntot + n0;
                #pragma unroll
                for (int nt = 0; nt < 8; nt++) {
                    int col = wn * 64 + nt * 8 + 2 * tg;
                    float v0 = acc[mt][nt][half * 2 + 0] + sBias[col];
                    float v1 = acc[mt][nt][half * 2 + 1] + sBias[col + 1];
                    if (DO_GELU) {
                        v0 = to_tf32(gelu_fast(v0));
                        v1 = to_tf32(gelu_fast(v1));
                    }
                    *(float2*)(Out + orow + col) = make_float2(v0, v1);
                }
            }
        }
    }
}

// ------------------------- launcher -------------------------
extern "C" void kernel_launch(void* const* d_in, const int* in_sizes, int n_in,
                              void* d_out, int out_size) {
    const float* x  = (const float*)d_in[0];
    const float* gw = (const float*)d_in[1];
    const float* gb = (const float*)d_in[2];
    const float* w1 = (const float*)d_in[3];
    const float* b1 = (const float*)d_in[4];
    const float* w2 = (const float*)d_in[5];
    const float* b2 = (const float*)d_in[6];
    float* out = (float*)d_out;

    void *p_w1t, *p_w2t, *p_xe, *p_h, *p_y;
    cudaGetSymbolAddress(&p_w1t, g_w1t);
    cudaGetSymbolAddress(&p_w2t, g_w2t);
    cudaGetSymbolAddress(&p_xe,  g_xe);
    cudaGetSymbolAddress(&p_h,   g_h);
    cudaGetSymbolAddress(&p_y,   g_y);

    size_t smem = (size_t)(STG * (AST + BST) + 256 + 8) * sizeof(float);
    cudaFuncSetAttribute(moe_ffn_gemm<1>,
                         cudaFuncAttributeMaxDynamicSharedMemorySize, (int)smem);
    cudaFuncSetAttribute(moe_ffn_gemm<0>,
                         cudaFuncAttributeMaxDynamicSharedMemorySize, (int)smem);

    moe_reset_kernel<<<1, 32>>>();
    // w1 [E][D][H] -> w1t [E][H][D]; w2 [E][H][D] -> w2t [E][D][H]; rna folded in
    moe_transpose_kernel<<<dim3(HH / 32, DD / 32, NE), dim3(32, 8)>>>(w1, (float*)p_w1t, DD, HH);
    moe_transpose_kernel<<<dim3(DD / 32, HH / 32, NE), dim3(32, 8)>>>(w2, (float*)p_w2t, HH, DD);
    moe_gate_kernel<<<NT / 8, 256>>>(x, gw, gb);
    moe_gather_kernel<<<dim3(NT, NE), 128>>>(x);
    // FFN1: g_h = rna(gelu(x @ w1 + b1))
    moe_ffn_gemm<1><<<dim3(64, HH / 256, NE), 512, smem>>>(
        (const float*)p_xe, (const float*)p_w1t, b1, (float*)p_h, DD, HH);
    // FFN2: g_y = h @ w2 + b2
    moe_ffn_gemm<0><<<dim3(64, DD / 256, NE), 512, smem>>>(
        (const float*)p_h, (const float*)p_w2t, b2, (float*)p_y, HH, DD);
    moe_combine_kernel<<<NT, 128>>>(out);
}

// round 10
// speedup vs baseline: 1.1101x; 1.1101x over previous
#include <cuda_runtime.h>
#include <cuda_bf16.h>
#include <cstdint>

#define NT   8192   // tokens
#define DD   1024   // model dim
#define HH   4096   // hidden dim
#define NE   8      // experts
#define NENT_PAD 16512

// ------------------------- device scratch (no allocs) -------------------------
__device__ float g_xe [(size_t)NENT_PAD * DD];  // gathered rna inputs per entry
__device__ float g_h  [(size_t)NENT_PAD * HH];  // gelu(x@w1+b1), rna'd
__device__ float g_y  [(size_t)NENT_PAD * DD];  // h@w2+b2
__device__ float g_wts[NT * 2];
__device__ int   g_list[NE * NT];
__device__ int   g_t2e [NT * 2];
__device__ int   g_cnt [NE];

// ------------------------- helpers -------------------------
__device__ __forceinline__ uint32_t s2u(const void* p) {
    return (uint32_t)__cvta_generic_to_shared(p);
}
__device__ __forceinline__ float to_tf32(float v) {
    uint32_t u; asm("cvt.rna.tf32.f32 %0, %1;" : "=r"(u) : "f"(v));
    return __uint_as_float(u);
}
// gelu(x) = x * sigmoid(2*0.79788456*(x + 0.044715 x^3)); matches tanh-gelu to ~1e-7
__device__ __forceinline__ float gelu_fast(float x) {
    float z = x * fmaf(0.10294324f, x * x, 2.30220822f);  // 2u*log2(e)
    float ex; asm("ex2.approx.f32 %0, %1;" : "=f"(ex) : "f"(-z));
    float r;  asm("rcp.approx.f32 %0, %1;" : "=f"(r)  : "f"(1.0f + ex));
    return x * r;
}
__device__ __forceinline__ void cp16(uint32_t s, const void* g) {
    asm volatile("cp.async.cg.shared.global [%0], [%1], 16;" :: "r"(s), "l"(g));
}
__device__ __forceinline__ void ldmA(uint32_t a[4], uint32_t addr) {
    asm volatile("ldmatrix.sync.aligned.m8n8.x4.shared.b16 {%0,%1,%2,%3}, [%4];"
                 : "=r"(a[0]), "=r"(a[1]), "=r"(a[2]), "=r"(a[3]) : "r"(addr));
}
__device__ __forceinline__ void mma8u(float d[4], const uint32_t a[4], const float b[2]) {
    asm volatile(
        "mma.sync.aligned.m16n8k8.row.col.f32.tf32.tf32.f32 "
        "{%0,%1,%2,%3}, {%4,%5,%6,%7}, {%8,%9}, {%0,%1,%2,%3};"
        : "+f"(d[0]), "+f"(d[1]), "+f"(d[2]), "+f"(d[3])
        : "r"(a[0]), "r"(a[1]), "r"(a[2]), "r"(a[3]),
          "r"(__float_as_uint(b[0])), "r"(__float_as_uint(b[1])));
}
__device__ __forceinline__ int expert_base(int e) {
    int b = 0;
    #pragma unroll
    for (int i = 0; i < NE; i++) b += (i < e) ? g_cnt[i] : 0;
    return b;
}

// ------------------------- small kernels -------------------------
__global__ void moe_reset_kernel() {
    if (threadIdx.x < NE) g_cnt[threadIdx.x] = 0;
}

__global__ void moe_gate_kernel(const float* __restrict__ x,
                                const float* __restrict__ gw,
                                const float* __restrict__ gb) {
    int warp = threadIdx.x >> 5, lane = threadIdx.x & 31;
    int t = blockIdx.x * 8 + warp;
    float acc[NE];
    #pragma unroll
    for (int e = 0; e < NE; e++) acc[e] = 0.f;
    const float* xr = x + (size_t)t * DD;
    for (int k = lane; k < DD; k += 32) {
        float xv = xr[k];
        const float4* g4 = (const float4*)(gw + (size_t)k * NE);
        float4 a = g4[0], b = g4[1];
        acc[0] = fmaf(xv, a.x, acc[0]); acc[1] = fmaf(xv, a.y, acc[1]);
        acc[2] = fmaf(xv, a.z, acc[2]); acc[3] = fmaf(xv, a.w, acc[3]);
        acc[4] = fmaf(xv, b.x, acc[4]); acc[5] = fmaf(xv, b.y, acc[5]);
        acc[6] = fmaf(xv, b.z, acc[6]); acc[7] = fmaf(xv, b.w, acc[7]);
    }
    #pragma unroll
    for (int off = 16; off > 0; off >>= 1)
        #pragma unroll
        for (int e = 0; e < NE; e++)
            acc[e] += __shfl_xor_sync(0xFFFFFFFFu, acc[e], off);
    if (lane == 0) {
        float l[NE];
        #pragma unroll
        for (int e = 0; e < NE; e++) l[e] = acc[e] + gb[e];
        int i0 = 0;
        #pragma unroll
        for (int e = 1; e < NE; e++) if (l[e] > l[i0]) i0 = e;
        int i1 = (i0 == 0) ? 1 : 0;
        #pragma unroll
        for (int e = 0; e < NE; e++) if (e != i0 && l[e] > l[i1]) i1 = e;
        float ex = __expf(l[i1] - l[i0]);
        float s  = 1.0f + ex;
        int s0 = atomicAdd(&g_cnt[i0], 1);
        g_list[i0 * NT + s0] = t * 2;
        int s1 = atomicAdd(&g_cnt[i1], 1);
        g_list[i1 * NT + s1] = t * 2 + 1;
        g_wts[t * 2]     = 1.0f / s;
        g_wts[t * 2 + 1] = ex / s;
    }
}

__global__ void moe_gather_kernel(const float* __restrict__ x) {
    int e = blockIdx.y;
    int cnt = g_cnt[e], base = expert_base(e);
    for (int slot = blockIdx.x; slot < cnt; slot += gridDim.x) {
        int tokj  = g_list[e * NT + slot];
        int entry = base + slot;
        if (threadIdx.x == 0) g_t2e[tokj] = entry;
        const float4* src = (const float4*)(x + (size_t)(tokj >> 1) * DD);
        float4*       dst = (float4*)(g_xe + (size_t)entry * DD);
        float4 v = src[threadIdx.x];              // 256 threads == DD/4
        v.x = to_tf32(v.x); v.y = to_tf32(v.y);
        v.z = to_tf32(v.z); v.w = to_tf32(v.w);
        dst[threadIdx.x] = v;
    }
}

__global__ void moe_combine_kernel(float* __restrict__ out) {
    int t = blockIdx.x;
    int e0 = g_t2e[2 * t], e1 = g_t2e[2 * t + 1];
    float w0 = g_wts[2 * t], w1 = g_wts[2 * t + 1];
    const float4* y0 = (const float4*)(g_y + (size_t)e0 * DD);
    const float4* y1 = (const float4*)(g_y + (size_t)e1 * DD);
    float4*       o  = (float4*)(out + (size_t)t * DD);
    int i = threadIdx.x;                          // 256 threads == DD/4
    float4 a = y0[i], b = y1[i];
    o[i] = make_float4(fmaf(w0, a.x, w1 * b.x), fmaf(w0, a.y, w1 * b.y),
                       fmaf(w0, a.z, w1 * b.z), fmaf(w0, a.w, w1 * b.w));
}

// ------------------------- mma.sync tf32 GEMM -------------------------
// CTA tile 128x256; warp tile 64x64 (grid 2m x 4n); K chunk 32.
// A: k-major stride 36 via ldmatrix.x4; B: raw [k][n] weights, stride 264,
// scalar fragments + in-register rna. 4-stage cp.async pipeline, 2-chunk
// groups: ONE wait_group + ONE barrier per 2 chunks. Register
// double-buffered fragments; in-group tail prefetch of chunk b's ks0.
#define AST (128 * 36)
#define BST (32 * 264)
#define STG 4

template <int DO_GELU>
__global__ void __launch_bounds__(256, 1)
moe_ffn_gemm(const float* __restrict__ A, const float* __restrict__ B,
             const float* __restrict__ bias, float* __restrict__ Out,
             int K, int Ntot) {
    int e   = blockIdx.z;
    int cnt = g_cnt[e];
    int m0  = blockIdx.x * 128;
    if (m0 >= cnt) return;
    int base = expert_base(e);
    int n0   = blockIdx.y * 256;

    extern __shared__ float sm[];
    float* sA    = sm;
    float* sB    = sm + STG * AST;
    float* sBias = sB + STG * BST;

    int tid  = threadIdx.x;
    int lane = tid & 31, w = tid >> 5;
    int g = lane >> 2, tg = lane & 3;
    int wm = w & 1, wn = w >> 1;

    int rsel = (lane & 7) + ((lane >> 3) & 1) * 8;
    int csel = (lane >> 4) * 4;
    uint32_t aLane = (uint32_t)(((wm * 64 + rsel) * 36 + csel) * 4);

    sBias[tid] = bias[(size_t)e * Ntot + n0 + tid];

    const float* Ab = A + (size_t)(base + m0) * K;
    const float* Bb = B + (size_t)e * K * Ntot + n0;
    int C = K >> 5;
    int G = C >> 1;   // 2-chunk groups; C is even (32 or 128)

    auto load_full = [&](int c, int s) {
        float* dA = sA + s * AST;
        const float* srcA = Ab + c * 32;
        #pragma unroll
        for (int j = 0; j < 4; j++) {
            int i = tid + j * 256;
            int m = i >> 3, kq = (i & 7) << 2;
            cp16(s2u(dA + m * 36 + kq), srcA + (size_t)m * K + kq);
        }
        float* dB = sB + s * BST;
        const float* srcB = Bb + (size_t)(c * 32) * Ntot;
        #pragma unroll
        for (int j = 0; j < 8; j++) {
            int i = tid + j * 256;
            int k = i >> 6, nq = (i & 63) << 2;
            cp16(s2u(dB + k * 264 + nq), srcB + (size_t)k * Ntot + nq);
        }
    };
    auto load_slice = [&](int c, int s, int part) {  // 3 cp16/part, parts 0..3
        {
            int i = tid + part * 256;
            int m = i >> 3, kq = (i & 7) << 2;
            cp16(s2u(sA + s * AST + m * 36 + kq), Ab + c * 32 + (size_t)m * K + kq);
        }
        #pragma unroll
        for (int jj = 0; jj < 2; jj++) {
            int i = tid + (part * 2 + jj) * 256;
            int k = i >> 6, nq = (i & 63) << 2;
            cp16(s2u(sB + s * BST + k * 264 + nq),
                 Bb + (size_t)(c * 32 + k) * Ntot + nq);
        }
    };

    auto ldfragA = [&](uint32_t af[4][4], int s, int ks) {
        uint32_t aBase = s2u(sA) + (uint32_t)s * (AST * 4) + aLane + (uint32_t)(ks * 32);
        #pragma unroll
        for (int mt = 0; mt < 4; mt++) ldmA(af[mt], aBase + (uint32_t)(mt * 2304));
    };
    auto ldfragB = [&](float bf[8][2], int s, int ks) {
        int kc = ks * 8 + tg;
        const float* p = sB + s * BST + kc * 264 + wn * 64 + g;
        #pragma unroll
        for (int nt = 0; nt < 8; nt++) {
            bf[nt][0] = to_tf32(p[nt * 8]);
            bf[nt][1] = to_tf32(p[4 * 264 + nt * 8]);
        }
    };

    // preload groups 0 and 1 (chunks 0..3 into stages 0..3), one commit each
    load_full(0, 0); load_full(1, 1);
    asm volatile("cp.async.commit_group;" ::: "memory");
    load_full(2, 2); load_full(3, 3);
    asm volatile("cp.async.commit_group;" ::: "memory");

    float acc[4][8][4];
    #pragma unroll
    for (int mt = 0; mt < 4; mt++)
        #pragma unroll
        for (int nt = 0; nt < 8; nt++)
            #pragma unroll
            for (int q = 0; q < 4; q++) acc[mt][nt][q] = 0.f;

    uint32_t af[2][4][4];
    float    bf[2][8][2];

    for (int j = 0; j < G; j++) {
        int s0 = (2 * j) & 3, s1 = s0 + 1;
        // certify current group's data (per-thread), then publish CTA-wide
        if (j == 0) { asm volatile("cp.async.wait_group 1;" ::: "memory"); }
        else        { asm volatile("cp.async.wait_group 0;" ::: "memory"); }
        __syncthreads();

        ldfragA(af[0], s0, 0); ldfragB(bf[0], s0, 0);

        bool ld = (j >= 1) && (j + 1 < G);       // group j+1 -> group j-1's stages
        int t0 = (s0 + 2) & 3, t1 = t0 + 1;

        // ---- chunk a = 2j (stage s0); front-load next group's 24 slices ----
        #pragma unroll
        for (int ks = 0; ks < 4; ks++) {
            int cur = ks & 1;
            if (ks < 3) { ldfragA(af[cur ^ 1], s0, ks + 1); ldfragB(bf[cur ^ 1], s0, ks + 1); }
            else        { ldfragA(af[cur ^ 1], s1, 0);      ldfragB(bf[cur ^ 1], s1, 0); }
            if (ld) { load_slice(2 * j + 2, t0, ks); load_slice(2 * j + 3, t1, ks); }
            #pragma unroll
            for (int mt = 0; mt < 4; mt++)
                #pragma unroll
                for (int nt = 0; nt < 8; nt++)
                    mma8u(acc[mt][nt], af[cur][mt], bf[cur][nt]);
        }
        if (ld) asm volatile("cp.async.commit_group;" ::: "memory");

        // ---- chunk b = 2j+1 (stage s1) ----
        #pragma unroll
        for (int ks = 0; ks < 4; ks++) {
            int cur = ks & 1;
            if (ks < 3) { ldfragA(af[cur ^ 1], s1, ks + 1); ldfragB(bf[cur ^ 1], s1, ks + 1); }
            #pragma unroll
            for (int mt = 0; mt < 4; mt++)
                #pragma unroll
                for (int nt = 0; nt < 8; nt++)
                    mma8u(acc[mt][nt], af[cur][mt], bf[cur][nt]);
        }
    }

    // epilogue: bias (+gelu+rna for FFN1), float2 stores
    #pragma unroll
    for (int mt = 0; mt < 4; mt++) {
        int r0 = m0 + wm * 64 + mt * 16 + g;
        #pragma unroll
        for (int half = 0; half < 2; half++) {
            int r = r0 + half * 8;
            if (r < cnt) {
                size_t orow = (size_t)(base + r) * Ntot + n0;
                #pragma unroll
                for (int nt = 0; nt < 8; nt++) {
                    int col = wn * 64 + nt * 8 + 2 * tg;
                    float v0 = acc[mt][nt][half * 2 + 0] + sBias[col];
                    float v1 = acc[mt][nt][half * 2 + 1] + sBias[col + 1];
                    if (DO_GELU) {
                        v0 = to_tf32(gelu_fast(v0));
                        v1 = to_tf32(gelu_fast(v1));
                    }
                    *(float2*)(Out + orow + col) = make_float2(v0, v1);
                }
            }
        }
    }
}

// ------------------------- launcher -------------------------
extern "C" void kernel_launch(void* const* d_in, const int* in_sizes, int n_in,
                              void* d_out, int out_size) {
    const float* x  = (const float*)d_in[0];
    const float* gw = (const float*)d_in[1];
    const float* gb = (const float*)d_in[2];
    const float* w1 = (const float*)d_in[3];
    const float* b1 = (const float*)d_in[4];
    const float* w2 = (const float*)d_in[5];
    const float* b2 = (const float*)d_in[6];
    float* out = (float*)d_out;

    void *p_xe, *p_h, *p_y;
    cudaGetSymbolAddress(&p_xe, g_xe);
    cudaGetSymbolAddress(&p_h,  g_h);
    cudaGetSymbolAddress(&p_y,  g_y);

    size_t smem = (size_t)(STG * (AST + BST) + 256) * sizeof(float);
    cudaFuncSetAttribute(moe_ffn_gemm<1>,
                         cudaFuncAttributeMaxDynamicSharedMemorySize, (int)smem);
    cudaFuncSetAttribute(moe_ffn_gemm<0>,
                         cudaFuncAttributeMaxDynamicSharedMemorySize, (int)smem);

    moe_reset_kernel<<<1, 32>>>();
    moe_gate_kernel<<<NT / 8, 256>>>(x, gw, gb);
    moe_gather_kernel<<<dim3(64, NE), 256>>>(x);
    // FFN1: g_h = rna(gelu(x @ w1 + b1))   (B = raw w1, rounded in-kernel)
    moe_ffn_gemm<1><<<dim3(64, HH / 256, NE), 256, smem>>>(
        (const float*)p_xe, w1, b1, (float*)p_h, DD, HH);
    // FFN2: g_y = h @ w2 + b2              (B = raw w2, rounded in-kernel)
    moe_ffn_gemm<0><<<dim3(64, DD / 256, NE), 256, smem>>>(
        (const float*)p_h, w2, b2, (float*)p_y, HH, DD);
    moe_combine_kernel<<<NT, 256>>>(out);
}